// round 7
// baseline (speedup 1.0000x reference)
#include <cuda_runtime.h>
#include <math.h>

#define NI 2304          // B*H*W
#define S_LEN 77
#define NQ 80            // N (query sequence)
#define HID 128
#define HEADS 8
#define DH 16
#define EPS 1e-6f

typedef unsigned long long u64;

// Scratch (device globals: allocation-free per harness rules)
__device__ float g_K[NI * S_LEN * HID];   // feature-mapped K
__device__ float g_V[NI * S_LEN * HID];   // raw V (no /S; factors cancel)
__device__ float g_Q[NI * NQ * HID];      // feature-mapped Q

__device__ __forceinline__ float fmap(float t) {
    // elu(t)+1 with alpha=1
    return t > 0.0f ? t + 1.0f : __expf(t);
}

// ---- packed f32x2 helpers (FFMA2 path: 2x fp32 FMA throughput) ----
__device__ __forceinline__ u64 pack2(float lo, float hi) {
    u64 r; asm("mov.b64 %0, {%1, %2};" : "=l"(r) : "f"(lo), "f"(hi)); return r;
}
__device__ __forceinline__ u64 fma2(u64 a, u64 b, u64 c) {
    u64 d; asm("fma.rn.f32x2 %0, %1, %2, %3;" : "=l"(d) : "l"(a), "l"(b), "l"(c)); return d;
}
__device__ __forceinline__ float2 unpack2(u64 v) {
    float2 f; asm("mov.b64 {%0, %1}, %2;" : "=f"(f.x), "=f"(f.y) : "l"(v)); return f;
}

// ---------------------------------------------------------------------------
// Tiled fp32 GEMM: C(M x 128) = gather(A)(M x KDEPTH) * W(KDEPTH x 128) + bias
// MODE 0: A = [x | guidance], out = g_K, fmap epilogue
// MODE 1: A = x,              out = g_V, no fmap
// MODE 2: A = query gathered, out = g_Q, fmap epilogue
// Block: 128x128 tile, 256 threads, 8x8 per-thread tile as 8x4 packed f32x2.
// ---------------------------------------------------------------------------
template<int KDEPTH, int MODE>
__global__ __launch_bounds__(256, 2)
void gemm_kernel(const float* __restrict__ A1, const float* __restrict__ A2,
                 const float* __restrict__ Wm, const float* __restrict__ bias)
{
    __shared__ float As[16][128];   // [k][m]
    __shared__ float Bs[16][128];   // [k][n]

    float* outp = (MODE == 0) ? g_K : (MODE == 1 ? g_V : g_Q);

    const int t       = threadIdx.x;
    const int m0      = blockIdx.x * 128;
    const int m_local = t & 127;
    const int kblk    = (t >> 7) * 8;        // 0 or 8
    const int m       = m0 + m_local;

    const float* arow;
    if (MODE == 2) {
        int ni  = m / NQ;
        int l   = m - ni * NQ;
        int b   = ni / 576;          // H*W = 576
        int rem = ni - b * 576;      // h*24 + w
        arow = A1 + (size_t)((b * NQ + l) * 576 + rem) * 256;
    } else {
        arow = A1 + (size_t)m * 128;
    }
    const float* arow2 = (MODE == 0) ? (A2 + (size_t)m * 128) : A1;

    const int tm = t & 15;    // row-tile index
    const int tn = t >> 4;    // col-tile index

    u64 acc2[8][4];
    #pragma unroll
    for (int i = 0; i < 8; i++)
        #pragma unroll
        for (int j = 0; j < 4; j++)
            acc2[i][j] = 0ULL;   // bit pattern of {0.0f, 0.0f}

    const int bkk = t >> 4;            // 0..15
    const int bc8 = (t & 15) * 8;      // 0,8,...,120

    for (int k0 = 0; k0 < KDEPTH; k0 += 16) {
        // ---- global loads into registers ----
        const int cbase = k0 + kblk;
        const float* src;
        if (MODE == 0)
            src = (cbase >= 128) ? (arow2 + (cbase - 128)) : (arow + cbase);
        else
            src = arow + cbase;
        const float4 a0 = *(const float4*)(src);
        const float4 a1 = *(const float4*)(src + 4);
        const float4 b0 = *(const float4*)(Wm + (size_t)(k0 + bkk) * 128 + bc8);
        const float4 b1 = *(const float4*)(Wm + (size_t)(k0 + bkk) * 128 + bc8 + 4);

        __syncthreads();
        As[kblk + 0][m_local] = a0.x;
        As[kblk + 1][m_local] = a0.y;
        As[kblk + 2][m_local] = a0.z;
        As[kblk + 3][m_local] = a0.w;
        As[kblk + 4][m_local] = a1.x;
        As[kblk + 5][m_local] = a1.y;
        As[kblk + 6][m_local] = a1.z;
        As[kblk + 7][m_local] = a1.w;
        *(float4*)&Bs[bkk][bc8]     = b0;
        *(float4*)&Bs[bkk][bc8 + 4] = b1;
        __syncthreads();

        // ---- 8x8 register-tile rank-16 update, packed f32x2 ----
        #pragma unroll
        for (int kk = 0; kk < 16; kk++) {
            float a[8];
            *(float4*)&a[0] = *(const float4*)&As[kk][tm * 8];
            *(float4*)&a[4] = *(const float4*)&As[kk][tm * 8 + 4];
            u64 bp[4];
            const u64* brow = (const u64*)&Bs[kk][tn * 8];
            bp[0] = brow[0]; bp[1] = brow[1]; bp[2] = brow[2]; bp[3] = brow[3];
            #pragma unroll
            for (int i = 0; i < 8; i++) {
                const u64 ad = pack2(a[i], a[i]);
                #pragma unroll
                for (int j = 0; j < 4; j++)
                    acc2[i][j] = fma2(ad, bp[j], acc2[i][j]);
            }
        }
    }

    // ---- epilogue: bias (+ feature map), vectorized store ----
    float bvals[8];
    #pragma unroll
    for (int j = 0; j < 8; j++) bvals[j] = bias[tn * 8 + j];

    #pragma unroll
    for (int i = 0; i < 8; i++) {
        const int row = m0 + tm * 8 + i;
        float vals[8];
        #pragma unroll
        for (int j = 0; j < 4; j++) {
            float2 p = unpack2(acc2[i][j]);
            float v0 = p.x + bvals[2 * j];
            float v1 = p.y + bvals[2 * j + 1];
            if (MODE != 1) { v0 = fmap(v0); v1 = fmap(v1); }
            vals[2 * j]     = v0;
            vals[2 * j + 1] = v1;
        }
        float* dst = outp + (size_t)row * 128 + tn * 8;
        *(float4*)dst       = *(float4*)&vals[0];
        *(float4*)(dst + 4) = *(float4*)&vals[4];
    }
}

// ---------------------------------------------------------------------------
// Attention reduction: 1 block per n, 128 threads (t = h*16 + dv).
// Pass 1 over S: Ksum[j] and per-head KV[d][dv], packed f32x2, unrolled for MLP.
// Pass 2: Q staged to smem in chunks of 16 rows (10 barriers instead of 160).
// ---------------------------------------------------------------------------
__global__ __launch_bounds__(128)
void attn_kernel(float* __restrict__ out)
{
    __shared__ float KV_s[HID * DH];    // [ (h*16+d) * 16 + dv ]
    __shared__ float Ksum_s[HID];
    __shared__ float Qs[16][HID];

    const int n  = blockIdx.x;
    const int t  = threadIdx.x;     // 0..127
    const int h  = t >> 4;
    const int dv = t & 15;

    const float* Kp = g_K + (size_t)n * (S_LEN * HID);
    const float* Vp = g_V + (size_t)n * (S_LEN * HID) + h * 16;

    u64 kv2[8];
    #pragma unroll
    for (int j = 0; j < 8; j++) kv2[j] = 0ULL;
    float ksum = 0.0f;

    #pragma unroll 4
    for (int s = 0; s < S_LEN; s++) {
        const float kd = Kp[s * HID + t];          // coalesced
        const float* vrow = Vp + s * HID;          // broadcast within head group
        const ulonglong2 p0 = *(const ulonglong2*)(vrow);
        const ulonglong2 p1 = *(const ulonglong2*)(vrow + 4);
        const ulonglong2 p2 = *(const ulonglong2*)(vrow + 8);
        const ulonglong2 p3 = *(const ulonglong2*)(vrow + 12);
        ksum += kd;
        const u64 kd2 = pack2(kd, kd);
        kv2[0] = fma2(kd2, p0.x, kv2[0]);
        kv2[1] = fma2(kd2, p0.y, kv2[1]);
        kv2[2] = fma2(kd2, p1.x, kv2[2]);
        kv2[3] = fma2(kd2, p1.y, kv2[3]);
        kv2[4] = fma2(kd2, p2.x, kv2[4]);
        kv2[5] = fma2(kd2, p2.y, kv2[5]);
        kv2[6] = fma2(kd2, p3.x, kv2[6]);
        kv2[7] = fma2(kd2, p3.y, kv2[7]);
    }
    Ksum_s[t] = ksum;
    #pragma unroll
    for (int j = 0; j < 8; j++) {
        float2 p = unpack2(kv2[j]);
        KV_s[t * 16 + 2 * j]     = p.x;   // thread t = (h, d) owns KV[h][d][*]
        KV_s[t * 16 + 2 * j + 1] = p.y;
    }

    float acc = 0.0f;
    const float* Qbase = g_Q + (size_t)n * (NQ * HID);
    const int hb = h * 16;

    #pragma unroll
    for (int c = 0; c < 5; c++) {
        __syncthreads();                      // prior chunk's reads done; KV ready at c=0
        #pragma unroll
        for (int i = 0; i < 16; i++)
            Qs[i][t] = Qbase[(c * 16 + i) * HID + t];   // coalesced, 16-deep MLP
        __syncthreads();
        #pragma unroll
        for (int i = 0; i < 16; i++) {
            float zs = EPS, tmp = 0.0f;
            #pragma unroll
            for (int d = 0; d < 16; d++) {
                const float qd = Qs[i][hb + d];
                zs  += qd * Ksum_s[hb + d];
                tmp += qd * KV_s[(hb + d) * 16 + dv];
            }
            acc += __fdividef(tmp, zs);
        }
    }

    out[(size_t)n * HID + t] = acc * (1.0f / NQ);
}

// ---------------------------------------------------------------------------
extern "C" void kernel_launch(void* const* d_in, const int* in_sizes, int n_in,
                              void* d_out, int out_size)
{
    const float* query = (const float*)d_in[0];
    const float* x     = (const float*)d_in[1];
    const float* guid  = (const float*)d_in[2];
    const float* Wq    = (const float*)d_in[3];
    const float* bq    = (const float*)d_in[4];
    const float* Wk    = (const float*)d_in[5];
    const float* bk    = (const float*)d_in[6];
    const float* Wv    = (const float*)d_in[7];
    const float* bv    = (const float*)d_in[8];
    float* out = (float*)d_out;

    // K projection: (NI*S_LEN) x 256 @ Wk -> fmap -> g_K   (177408 rows = 1386*128)
    gemm_kernel<256, 0><<<1386, 256>>>(x, guid, Wk, bk);
    // V projection: (NI*S_LEN) x 128 @ Wv -> g_V
    gemm_kernel<128, 1><<<1386, 256>>>(x, nullptr, Wv, bv);
    // Q projection: (NI*NQ) x 256 @ Wq -> fmap -> g_Q      (184320 rows = 1440*128)
    gemm_kernel<256, 2><<<1440, 256>>>(query, nullptr, Wq, bq);
    // Attention reduction -> out (NI x 128)
    attn_kernel<<<NI, 128>>>(out);
}

// round 10
// speedup vs baseline: 3.2539x; 3.2539x over previous
#include <cuda_runtime.h>
#include <cuda_bf16.h>
#include <math.h>
#include <stdint.h>

#define NI 2304          // B*H*W
#define S_LEN 77
#define NQ 80
#define HID 128
#define EPS 1e-6f

typedef unsigned long long u64;

// ---------------- scratch (device globals; allocation-free) ----------------
__device__ float g_K[NI * S_LEN * HID];
__device__ float g_V[NI * S_LEN * HID];
__device__ float g_Q[NI * NQ * HID];

__device__ __forceinline__ float fmap(float t) {
    return t > 0.0f ? t + 1.0f : __expf(t);   // elu+1
}

__device__ __forceinline__ uint32_t s2u(const void* p) {
    uint32_t a;
    asm("{ .reg .u64 t; cvta.to.shared.u64 t, %1; cvt.u32.u64 %0, t; }" : "=r"(a) : "l"(p));
    return a;
}

__device__ __forceinline__ void split_bf16(float v, __nv_bfloat16& hi, __nv_bfloat16& lo) {
    hi = __float2bfloat16(v);
    lo = __float2bfloat16(v - __bfloat162float(hi));
}

__device__ __forceinline__ u64 pack4(__nv_bfloat16 a, __nv_bfloat16 b,
                                     __nv_bfloat16 c, __nv_bfloat16 d) {
    return (u64)__bfloat16_as_ushort(a)
         | ((u64)__bfloat16_as_ushort(b) << 16)
         | ((u64)__bfloat16_as_ushort(c) << 32)
         | ((u64)__bfloat16_as_ushort(d) << 48);
}

#define LDSM_X4(r0, r1, r2, r3, addr) \
    asm volatile("ldmatrix.sync.aligned.m8n8.x4.shared.b16 {%0,%1,%2,%3}, [%4];" \
        : "=r"(r0), "=r"(r1), "=r"(r2), "=r"(r3) : "r"(addr))

#define LDSM_X4T(r0, r1, r2, r3, addr) \
    asm volatile("ldmatrix.sync.aligned.m8n8.x4.trans.shared.b16 {%0,%1,%2,%3}, [%4];" \
        : "=r"(r0), "=r"(r1), "=r"(r2), "=r"(r3) : "r"(addr))

#define MMA_BF16(d, a, b0, b1) \
    asm volatile("mma.sync.aligned.m16n8k16.row.col.f32.bf16.bf16.f32 " \
        "{%0,%1,%2,%3}, {%4,%5,%6,%7}, {%8,%9}, {%0,%1,%2,%3};" \
        : "+f"((d)[0]), "+f"((d)[1]), "+f"((d)[2]), "+f"((d)[3]) \
        : "r"((a)[0]), "r"((a)[1]), "r"((a)[2]), "r"((a)[3]), "r"(b0), "r"(b1))

// ---------------------------------------------------------------------------
// HMMA bf16 split GEMM: C(M x 128) = gather(A)(M x KDEPTH) @ W + bias
// MODE 0: A=[x|guidance]->g_K (fmap); MODE 1: A=x->g_V; MODE 2: query->g_Q (fmap)
// CTA: 128x128, 8 warps (4 M-slots x 2 N-slots), warp tile 32x64, K-chunk 32.
// 3-term split: Ah*Bh + Ah*Bl + Al*Bh.
// ---------------------------------------------------------------------------
#define A_STR 40      // bf16 elems per A row (32 + 8 pad)  -> 80B, 5x16B
#define B_STR 136     // bf16 elems per B row (128 + 8 pad) -> 272B, 17x16B

template<int KDEPTH, int MODE>
__global__ __launch_bounds__(256, 2)
void gemm_mma(const float* __restrict__ A1, const float* __restrict__ A2,
              const float* __restrict__ W, const float* __restrict__ bias)
{
    __shared__ __nv_bfloat16 Ah_s[128 * A_STR], Al_s[128 * A_STR];
    __shared__ __nv_bfloat16 Bh_s[32 * B_STR],  Bl_s[32 * B_STR];
    __shared__ float bias_s[128];

    float* outp = (MODE == 0) ? g_K : (MODE == 1 ? g_V : g_Q);

    const int t    = threadIdx.x;
    const int lane = t & 31;
    const int wid  = t >> 5;
    const int wm   = wid & 3;        // M slot (32 rows)
    const int wn   = wid >> 2;       // N slot (64 cols)
    const int m0   = blockIdx.x * 128;

    if (t < 128) bias_s[t] = bias[t];

    const uint32_t sAh = s2u(Ah_s), sAl = s2u(Al_s);
    const uint32_t sBh = s2u(Bh_s), sBl = s2u(Bl_s);

    float acc[2][8][4];
    #pragma unroll
    for (int mt = 0; mt < 2; mt++)
        #pragma unroll
        for (int nt = 0; nt < 8; nt++)
            #pragma unroll
            for (int j = 0; j < 4; j++) acc[mt][nt][j] = 0.0f;

    // ldmatrix lane address components (same formula for A and B-trans)
    const int l15 = lane & 15;
    const int l16 = (lane >> 4) * 8;

    for (int c = 0; c < KDEPTH / 32; c++) {
        // ---- fill A hi/lo: 128 rows x 32 k (1024 float4 loads) ----
        #pragma unroll
        for (int it = 0; it < 4; it++) {
            int g  = t + it * 256;          // 0..1023
            int r  = g >> 3;                // row 0..127
            int k4 = (g & 7) << 2;          // 0,4,...,28
            int m  = m0 + r;
            int kg = c * 32 + k4;
            const float* src;
            if (MODE == 2) {
                int ni = m / NQ; int l = m - ni * NQ;
                int b = ni / 576; int rem = ni - b * 576;
                src = A1 + (size_t)((b * NQ + l) * 576 + rem) * 256 + kg;
            } else if (MODE == 0) {
                src = (kg >= 128) ? (A2 + (size_t)m * 128 + (kg - 128))
                                  : (A1 + (size_t)m * 128 + kg);
            } else {
                src = A1 + (size_t)m * 128 + kg;
            }
            float4 v = *(const float4*)src;
            __nv_bfloat16 h0,h1,h2,h3, e0,e1,e2,e3;
            split_bf16(v.x, h0, e0); split_bf16(v.y, h1, e1);
            split_bf16(v.z, h2, e2); split_bf16(v.w, h3, e3);
            int off = r * (A_STR * 2) + k4 * 2;   // bytes
            *(u64*)((char*)Ah_s + off) = pack4(h0, h1, h2, h3);
            *(u64*)((char*)Al_s + off) = pack4(e0, e1, e2, e3);
        }
        // ---- fill B hi/lo: 32 k-rows x 128 n (1024 float4 loads, L2-hot) ----
        #pragma unroll
        for (int it = 0; it < 4; it++) {
            int g  = t + it * 256;
            int k  = g >> 5;                // 0..31
            int n4 = (g & 31) << 2;         // 0..124
            float4 v = *(const float4*)(W + (size_t)(c * 32 + k) * 128 + n4);
            __nv_bfloat16 h0,h1,h2,h3, e0,e1,e2,e3;
            split_bf16(v.x, h0, e0); split_bf16(v.y, h1, e1);
            split_bf16(v.z, h2, e2); split_bf16(v.w, h3, e3);
            int off = k * (B_STR * 2) + n4 * 2;
            *(u64*)((char*)Bh_s + off) = pack4(h0, h1, h2, h3);
            *(u64*)((char*)Bl_s + off) = pack4(e0, e1, e2, e3);
        }
        __syncthreads();

        // ---- compute: 2 k16 steps ----
        #pragma unroll
        for (int ks = 0; ks < 2; ks++) {
            // B fragments: 4 n16 groups, each x4 = two n8 tiles
            uint32_t bh[4][4], bl[4][4];
            #pragma unroll
            for (int ng = 0; ng < 4; ng++) {
                uint32_t ba = (uint32_t)((ks * 16 + l15) * (B_STR * 2)
                             + (wn * 64 + ng * 16 + l16) * 2);
                LDSM_X4T(bh[ng][0], bh[ng][1], bh[ng][2], bh[ng][3], sBh + ba);
                LDSM_X4T(bl[ng][0], bl[ng][1], bl[ng][2], bl[ng][3], sBl + ba);
            }
            #pragma unroll
            for (int mt = 0; mt < 2; mt++) {
                uint32_t aa = (uint32_t)((wm * 32 + mt * 16 + l15) * (A_STR * 2)
                             + (ks * 16 + l16) * 2);
                uint32_t ah[4], al[4];
                LDSM_X4(ah[0], ah[1], ah[2], ah[3], sAh + aa);
                LDSM_X4(al[0], al[1], al[2], al[3], sAl + aa);
                #pragma unroll
                for (int nt = 0; nt < 8; nt++) {
                    const int ng = nt >> 1, hf = (nt & 1) * 2;
                    MMA_BF16(acc[mt][nt], ah, bh[ng][hf], bh[ng][hf + 1]);
                    MMA_BF16(acc[mt][nt], ah, bl[ng][hf], bl[ng][hf + 1]);
                    MMA_BF16(acc[mt][nt], al, bh[ng][hf], bh[ng][hf + 1]);
                }
            }
        }
        __syncthreads();
    }

    // ---- epilogue: bias (+fmap), direct global stores ----
    const int r4 = lane >> 2;          // 0..7
    const int c2 = (lane & 3) * 2;     // 0,2,4,6
    #pragma unroll
    for (int mt = 0; mt < 2; mt++) {
        #pragma unroll
        for (int nt = 0; nt < 8; nt++) {
            const int col = wn * 64 + nt * 8 + c2;
            const float b0 = bias_s[col], b1 = bias_s[col + 1];
            const int row0 = m0 + wm * 32 + mt * 16 + r4;
            float2 o0, o1;
            o0.x = acc[mt][nt][0] + b0;  o0.y = acc[mt][nt][1] + b1;
            o1.x = acc[mt][nt][2] + b0;  o1.y = acc[mt][nt][3] + b1;
            if (MODE != 1) {
                o0.x = fmap(o0.x); o0.y = fmap(o0.y);
                o1.x = fmap(o1.x); o1.y = fmap(o1.y);
            }
            *(float2*)(outp + (size_t)row0 * 128 + col)       = o0;
            *(float2*)(outp + (size_t)(row0 + 8) * 128 + col) = o1;
        }
    }
}

// ---------------------------------------------------------------------------
// Attention reduction (unchanged, measured 148us)
// ---------------------------------------------------------------------------
__device__ __forceinline__ u64 pack2(float lo, float hi) {
    u64 r; asm("mov.b64 %0, {%1, %2};" : "=l"(r) : "f"(lo), "f"(hi)); return r;
}
__device__ __forceinline__ u64 fma2(u64 a, u64 b, u64 c) {
    u64 d; asm("fma.rn.f32x2 %0, %1, %2, %3;" : "=l"(d) : "l"(a), "l"(b), "l"(c)); return d;
}
__device__ __forceinline__ float2 unpack2(u64 v) {
    float2 f; asm("mov.b64 {%0, %1}, %2;" : "=f"(f.x), "=f"(f.y) : "l"(v)); return f;
}

__global__ __launch_bounds__(128)
void attn_kernel(float* __restrict__ out)
{
    __shared__ float KV_s[HID * 16];
    __shared__ float Ksum_s[HID];
    __shared__ float Qs[16][HID];

    const int n  = blockIdx.x;
    const int t  = threadIdx.x;
    const int h  = t >> 4;
    const int dv = t & 15;

    const float* Kp = g_K + (size_t)n * (S_LEN * HID);
    const float* Vp = g_V + (size_t)n * (S_LEN * HID) + h * 16;

    u64 kv2[8];
    #pragma unroll
    for (int j = 0; j < 8; j++) kv2[j] = 0ULL;
    float ksum = 0.0f;

    #pragma unroll 4
    for (int s = 0; s < S_LEN; s++) {
        const float kd = Kp[s * HID + t];
        const float* vrow = Vp + s * HID;
        const ulonglong2 p0 = *(const ulonglong2*)(vrow);
        const ulonglong2 p1 = *(const ulonglong2*)(vrow + 4);
        const ulonglong2 p2 = *(const ulonglong2*)(vrow + 8);
        const ulonglong2 p3 = *(const ulonglong2*)(vrow + 12);
        ksum += kd;
        const u64 kd2 = pack2(kd, kd);
        kv2[0] = fma2(kd2, p0.x, kv2[0]);
        kv2[1] = fma2(kd2, p0.y, kv2[1]);
        kv2[2] = fma2(kd2, p1.x, kv2[2]);
        kv2[3] = fma2(kd2, p1.y, kv2[3]);
        kv2[4] = fma2(kd2, p2.x, kv2[4]);
        kv2[5] = fma2(kd2, p2.y, kv2[5]);
        kv2[6] = fma2(kd2, p3.x, kv2[6]);
        kv2[7] = fma2(kd2, p3.y, kv2[7]);
    }
    Ksum_s[t] = ksum;
    #pragma unroll
    for (int j = 0; j < 8; j++) {
        float2 p = unpack2(kv2[j]);
        KV_s[t * 16 + 2 * j]     = p.x;
        KV_s[t * 16 + 2 * j + 1] = p.y;
    }

    float acc = 0.0f;
    const float* Qbase = g_Q + (size_t)n * (NQ * HID);
    const int hb = h * 16;

    #pragma unroll
    for (int c = 0; c < 5; c++) {
        __syncthreads();
        #pragma unroll
        for (int i = 0; i < 16; i++)
            Qs[i][t] = Qbase[(c * 16 + i) * HID + t];
        __syncthreads();
        #pragma unroll
        for (int i = 0; i < 16; i++) {
            float zs = EPS, tmp = 0.0f;
            #pragma unroll
            for (int d = 0; d < 16; d++) {
                const float qd = Qs[i][hb + d];
                zs  += qd * Ksum_s[hb + d];
                tmp += qd * KV_s[(hb + d) * 16 + dv];
            }
            acc += __fdividef(tmp, zs);
        }
    }

    out[(size_t)n * HID + t] = acc * (1.0f / NQ);
}

// ---------------------------------------------------------------------------
extern "C" void kernel_launch(void* const* d_in, const int* in_sizes, int n_in,
                              void* d_out, int out_size)
{
    const float* query = (const float*)d_in[0];
    const float* x     = (const float*)d_in[1];
    const float* guid  = (const float*)d_in[2];
    const float* Wq    = (const float*)d_in[3];
    const float* bq    = (const float*)d_in[4];
    const float* Wk    = (const float*)d_in[5];
    const float* bk    = (const float*)d_in[6];
    const float* Wv    = (const float*)d_in[7];
    const float* bv    = (const float*)d_in[8];
    float* out = (float*)d_out;

    // K projection: (NI*S_LEN) x 256 @ Wk -> fmap -> g_K   (177408 = 1386*128)
    gemm_mma<256, 0><<<1386, 256>>>(x, guid, Wk, bk);
    // V projection: (NI*S_LEN) x 128 @ Wv -> g_V
    gemm_mma<128, 1><<<1386, 256>>>(x, nullptr, Wv, bv);
    // Q projection: (NI*NQ) x 256 @ Wq -> fmap -> g_Q      (184320 = 1440*128)
    gemm_mma<256, 2><<<1440, 256>>>(query, nullptr, Wq, bq);
    // Attention reduction -> out
    attn_kernel<<<NI, 128>>>(out);
}

// round 12
// speedup vs baseline: 3.4407x; 1.0574x over previous
#include <cuda_runtime.h>
#include <cuda_bf16.h>
#include <math.h>
#include <stdint.h>

#define NI 2304          // B*H*W
#define S_LEN 77
#define NQ 80
#define HID 128
#define EPS 1e-6f

typedef unsigned long long u64;

// ---------------- scratch (device globals; allocation-free) ----------------
__device__ float g_K[NI * S_LEN * HID];
__device__ float g_V[NI * S_LEN * HID];
__device__ float g_Q[NI * NQ * HID];

// Pre-split padded weight images: per 32-K chunk, 32 rows x 136 (128 + 8 pad) bf16.
#define B_STR 136
#define CHUNK_ELEMS (32 * B_STR)          // 4352 elems = 8704 bytes
__device__ __align__(16) __nv_bfloat16 g_Bk_hi[8 * CHUNK_ELEMS], g_Bk_lo[8 * CHUNK_ELEMS];
__device__ __align__(16) __nv_bfloat16 g_Bv_hi[4 * CHUNK_ELEMS], g_Bv_lo[4 * CHUNK_ELEMS];
__device__ __align__(16) __nv_bfloat16 g_Bq_hi[8 * CHUNK_ELEMS], g_Bq_lo[8 * CHUNK_ELEMS];

__device__ __forceinline__ float fmap(float t) {
    return t > 0.0f ? t + 1.0f : __expf(t);   // elu+1
}

__device__ __forceinline__ uint32_t s2u(const void* p) {
    uint32_t a;
    asm("{ .reg .u64 t; cvta.to.shared.u64 t, %1; cvt.u32.u64 %0, t; }" : "=r"(a) : "l"(p));
    return a;
}

#define LDSM_X4(r0, r1, r2, r3, addr) \
    asm volatile("ldmatrix.sync.aligned.m8n8.x4.shared.b16 {%0,%1,%2,%3}, [%4];" \
        : "=r"(r0), "=r"(r1), "=r"(r2), "=r"(r3) : "r"(addr))

#define LDSM_X4T(r0, r1, r2, r3, addr) \
    asm volatile("ldmatrix.sync.aligned.m8n8.x4.trans.shared.b16 {%0,%1,%2,%3}, [%4];" \
        : "=r"(r0), "=r"(r1), "=r"(r2), "=r"(r3) : "r"(addr))

#define MMA_BF16(d, a, b0, b1) \
    asm volatile("mma.sync.aligned.m16n8k16.row.col.f32.bf16.bf16.f32 " \
        "{%0,%1,%2,%3}, {%4,%5,%6,%7}, {%8,%9}, {%0,%1,%2,%3};" \
        : "+f"((d)[0]), "+f"((d)[1]), "+f"((d)[2]), "+f"((d)[3]) \
        : "r"((a)[0]), "r"((a)[1]), "r"((a)[2]), "r"((a)[3]), "r"(b0), "r"(b1))

#define CP_ASYNC16(dst, src) \
    asm volatile("cp.async.cg.shared.global [%0], [%1], 16;" :: "r"(dst), "l"(src) : "memory")
#define CP_COMMIT() asm volatile("cp.async.commit_group;" ::: "memory")
#define CP_WAIT0()  asm volatile("cp.async.wait_group 0;"  ::: "memory")

// ---------------------------------------------------------------------------
// Weight prep: truncation-split W(KDEPTH x 128) -> padded bf16 hi/lo chunk images.
// MODE selects the destination device globals INSIDE device code (host must not
// take the address of __device__ symbols).
// ---------------------------------------------------------------------------
template<int MODE>
__global__ void prep_w(const float* __restrict__ W)
{
    constexpr int NCHUNK = (MODE == 1) ? 4 : 8;
    __nv_bfloat16* hi = (MODE == 0) ? g_Bk_hi : (MODE == 1 ? g_Bv_hi : g_Bq_hi);
    __nv_bfloat16* lo = (MODE == 0) ? g_Bk_lo : (MODE == 1 ? g_Bv_lo : g_Bq_lo);

    int idx = blockIdx.x * 256 + threadIdx.x;   // one per element
    if (idx >= NCHUNK * 4096) return;
    int c = idx >> 12;
    int r = (idx >> 7) & 31;
    int n = idx & 127;
    float v = W[(c * 32 + r) * 128 + n];
    uint32_t vb = __float_as_uint(v);
    float hf = __uint_as_float(vb & 0xFFFF0000u);   // truncation hi
    hi[(c * 32 + r) * B_STR + n] = __ushort_as_bfloat16((unsigned short)(vb >> 16));
    lo[(c * 32 + r) * B_STR + n] = __float2bfloat16(v - hf);   // exact residual, RN
}

// ---------------------------------------------------------------------------
// HMMA bf16 split GEMM: C(M x 128) = gather(A)(M x KDEPTH) @ W + bias
// MODE 0: A=[x|guidance]->g_K (fmap); MODE 1: A=x->g_V; MODE 2: query->g_Q (fmap)
// CTA 128x128, 8 warps (4 M x 2 N slots), warp tile 32x64, K-chunk 32.
// B loaded via cp.async from pre-split images; A split inline (PRMT/CVT path).
// ---------------------------------------------------------------------------
#define A_STR 40      // bf16 elems per A row (32 + 8 pad) -> 80B row

template<int KDEPTH, int MODE>
__global__ __launch_bounds__(256, 2)
void gemm_mma(const float* __restrict__ A1, const float* __restrict__ A2,
              const float* __restrict__ bias)
{
    __shared__ __align__(16) __nv_bfloat16 Ah_s[128 * A_STR], Al_s[128 * A_STR];
    __shared__ __align__(16) __nv_bfloat16 Bh_s[32 * B_STR],  Bl_s[32 * B_STR];
    __shared__ float bias_s[128];

    float* outp = (MODE == 0) ? g_K : (MODE == 1 ? g_V : g_Q);
    const __nv_bfloat16* img_hi = (MODE == 0) ? g_Bk_hi : (MODE == 1 ? g_Bv_hi : g_Bq_hi);
    const __nv_bfloat16* img_lo = (MODE == 0) ? g_Bk_lo : (MODE == 1 ? g_Bv_lo : g_Bq_lo);

    const int t    = threadIdx.x;
    const int lane = t & 31;
    const int wid  = t >> 5;
    const int wm   = wid & 3;        // M slot (32 rows)
    const int wn   = wid >> 2;       // N slot (64 cols)
    const int m0   = blockIdx.x * 128;

    if (t < 128) bias_s[t] = bias[t];

    const uint32_t sAh = s2u(Ah_s), sAl = s2u(Al_s);
    const uint32_t sBh = s2u(Bh_s), sBl = s2u(Bl_s);

    // Hoisted A row pointers (4 rows per thread: r = (t>>3) + it*32)
    const int k4     = (t & 7) << 2;            // 0,4,...,28 (same for all it)
    const int r_base = t >> 3;
    const float* rowp[4];
    const float* rowg[4];
    #pragma unroll
    for (int it = 0; it < 4; it++) {
        int r = r_base + it * 32;
        int m = m0 + r;
        if (MODE == 2) {
            int ni = m / NQ; int l = m - ni * NQ;
            int b = ni / 576; int rem = ni - b * 576;
            rowp[it] = A1 + (size_t)((b * NQ + l) * 576 + rem) * 256;
        } else {
            rowp[it] = A1 + (size_t)m * 128;
            if (MODE == 0) rowg[it] = A2 + (size_t)m * 128;
        }
    }

    float acc[2][8][4];
    #pragma unroll
    for (int mt = 0; mt < 2; mt++)
        #pragma unroll
        for (int nt = 0; nt < 8; nt++)
            #pragma unroll
            for (int j = 0; j < 4; j++) acc[mt][nt][j] = 0.0f;

    const int l15 = lane & 15;
    const int l16 = (lane >> 4) * 8;

    for (int c = 0; c < KDEPTH / 32; c++) {
        // ---- B fill: cp.async 16B copies from pre-split images (1088 total) ----
        {
            const char* ih = (const char*)img_hi + (size_t)c * 8704;
            const char* il = (const char*)img_lo + (size_t)c * 8704;
            for (int i = t; i < 1088; i += 256) {
                bool isHi = i < 544;
                int o = (isHi ? i : i - 544) * 16;
                uint32_t dst = (isHi ? sBh : sBl) + o;
                const char* src = (isHi ? ih : il) + o;
                CP_ASYNC16(dst, src);
            }
            CP_COMMIT();
        }
        // ---- A fill: 128 rows x 32 k, truncation split (PRMT + FSUB + CVT) ----
        const int kg = c * 32 + k4;
        #pragma unroll
        for (int it = 0; it < 4; it++) {
            const float* src;
            if (MODE == 0)
                src = (kg >= 128) ? (rowg[it] + (kg - 128)) : (rowp[it] + kg);
            else
                src = rowp[it] + kg;
            float4 v = *(const float4*)src;
            uint32_t bx = __float_as_uint(v.x), by = __float_as_uint(v.y);
            uint32_t bz = __float_as_uint(v.z), bw = __float_as_uint(v.w);
            uint32_t hi01, hi23, lo01, lo23;
            asm("prmt.b32 %0, %1, %2, 0x7632;" : "=r"(hi01) : "r"(bx), "r"(by));
            asm("prmt.b32 %0, %1, %2, 0x7632;" : "=r"(hi23) : "r"(bz), "r"(bw));
            float lx = v.x - __uint_as_float(bx & 0xFFFF0000u);
            float ly = v.y - __uint_as_float(by & 0xFFFF0000u);
            float lz = v.z - __uint_as_float(bz & 0xFFFF0000u);
            float lw = v.w - __uint_as_float(bw & 0xFFFF0000u);
            asm("cvt.rn.bf16x2.f32 %0, %1, %2;" : "=r"(lo01) : "f"(ly), "f"(lx));
            asm("cvt.rn.bf16x2.f32 %0, %1, %2;" : "=r"(lo23) : "f"(lw), "f"(lz));
            int off = (r_base + it * 32) * (A_STR * 2) + k4 * 2;
            *(u64*)((char*)Ah_s + off) = (u64)hi01 | ((u64)hi23 << 32);
            *(u64*)((char*)Al_s + off) = (u64)lo01 | ((u64)lo23 << 32);
        }
        CP_WAIT0();
        __syncthreads();

        // ---- compute: 2 k16 steps ----
        #pragma unroll
        for (int ks = 0; ks < 2; ks++) {
            uint32_t bh[4][4], bl[4][4];
            #pragma unroll
            for (int ng = 0; ng < 4; ng++) {
                uint32_t ba = (uint32_t)((ks * 16 + l15) * (B_STR * 2)
                             + (wn * 64 + ng * 16 + l16) * 2);
                LDSM_X4T(bh[ng][0], bh[ng][1], bh[ng][2], bh[ng][3], sBh + ba);
                LDSM_X4T(bl[ng][0], bl[ng][1], bl[ng][2], bl[ng][3], sBl + ba);
            }
            #pragma unroll
            for (int mt = 0; mt < 2; mt++) {
                uint32_t aa = (uint32_t)((wm * 32 + mt * 16 + l15) * (A_STR * 2)
                             + (ks * 16 + l16) * 2);
                uint32_t ah[4], al[4];
                LDSM_X4(ah[0], ah[1], ah[2], ah[3], sAh + aa);
                LDSM_X4(al[0], al[1], al[2], al[3], sAl + aa);
                #pragma unroll
                for (int nt = 0; nt < 8; nt++) {
                    const int ng = nt >> 1, hf = (nt & 1) * 2;
                    MMA_BF16(acc[mt][nt], ah, bh[ng][hf], bh[ng][hf + 1]);
                    MMA_BF16(acc[mt][nt], ah, bl[ng][hf], bl[ng][hf + 1]);
                    MMA_BF16(acc[mt][nt], al, bh[ng][hf], bh[ng][hf + 1]);
                }
            }
        }
        __syncthreads();
    }

    // ---- epilogue: bias (+fmap), direct global stores ----
    const int r4 = lane >> 2;
    const int c2 = (lane & 3) * 2;
    #pragma unroll
    for (int mt = 0; mt < 2; mt++) {
        #pragma unroll
        for (int nt = 0; nt < 8; nt++) {
            const int col = wn * 64 + nt * 8 + c2;
            const float b0 = bias_s[col], b1 = bias_s[col + 1];
            const int row0 = m0 + wm * 32 + mt * 16 + r4;
            float2 o0, o1;
            o0.x = acc[mt][nt][0] + b0;  o0.y = acc[mt][nt][1] + b1;
            o1.x = acc[mt][nt][2] + b0;  o1.y = acc[mt][nt][3] + b1;
            if (MODE != 1) {
                o0.x = fmap(o0.x); o0.y = fmap(o0.y);
                o1.x = fmap(o1.x); o1.y = fmap(o1.y);
            }
            *(float2*)(outp + (size_t)row0 * 128 + col)       = o0;
            *(float2*)(outp + (size_t)(row0 + 8) * 128 + col) = o1;
        }
    }
}

// ---------------------------------------------------------------------------
// Attention reduction. Pass 1 (FFMA2 outer products); pass 2 with Ksum/KV
// hoisted into registers (loop-invariant over all 80 l-iterations).
// ---------------------------------------------------------------------------
__device__ __forceinline__ u64 pack2(float lo, float hi) {
    u64 r; asm("mov.b64 %0, {%1, %2};" : "=l"(r) : "f"(lo), "f"(hi)); return r;
}
__device__ __forceinline__ u64 fma2(u64 a, u64 b, u64 c) {
    u64 d; asm("fma.rn.f32x2 %0, %1, %2, %3;" : "=l"(d) : "l"(a), "l"(b), "l"(c)); return d;
}
__device__ __forceinline__ float2 unpack2(u64 v) {
    float2 f; asm("mov.b64 {%0, %1}, %2;" : "=f"(f.x), "=f"(f.y) : "l"(v)); return f;
}

__global__ __launch_bounds__(128)
void attn_kernel(float* __restrict__ out)
{
    __shared__ float KV_s[HID * 16];
    __shared__ float Ksum_s[HID];
    __shared__ float Qs[16][HID];

    const int n  = blockIdx.x;
    const int t  = threadIdx.x;
    const int h  = t >> 4;
    const int dv = t & 15;

    const float* Kp = g_K + (size_t)n * (S_LEN * HID);
    const float* Vp = g_V + (size_t)n * (S_LEN * HID) + h * 16;

    u64 kv2[8];
    #pragma unroll
    for (int j = 0; j < 8; j++) kv2[j] = 0ULL;
    float ksum = 0.0f;

    #pragma unroll 4
    for (int s = 0; s < S_LEN; s++) {
        const float kd = Kp[s * HID + t];
        const float* vrow = Vp + s * HID;
        const ulonglong2 p0 = *(const ulonglong2*)(vrow);
        const ulonglong2 p1 = *(const ulonglong2*)(vrow + 4);
        const ulonglong2 p2 = *(const ulonglong2*)(vrow + 8);
        const ulonglong2 p3 = *(const ulonglong2*)(vrow + 12);
        ksum += kd;
        const u64 kd2 = pack2(kd, kd);
        kv2[0] = fma2(kd2, p0.x, kv2[0]);
        kv2[1] = fma2(kd2, p0.y, kv2[1]);
        kv2[2] = fma2(kd2, p1.x, kv2[2]);
        kv2[3] = fma2(kd2, p1.y, kv2[3]);
        kv2[4] = fma2(kd2, p2.x, kv2[4]);
        kv2[5] = fma2(kd2, p2.y, kv2[5]);
        kv2[6] = fma2(kd2, p3.x, kv2[6]);
        kv2[7] = fma2(kd2, p3.y, kv2[7]);
    }
    Ksum_s[t] = ksum;
    #pragma unroll
    for (int j = 0; j < 8; j++) {
        float2 p = unpack2(kv2[j]);
        KV_s[t * 16 + 2 * j]     = p.x;
        KV_s[t * 16 + 2 * j + 1] = p.y;
    }
    __syncthreads();

    // Hoist loop-invariant Ksum and KV column into registers
    const int hb = h * 16;
    float ks_r[16], kvc[16];
    #pragma unroll
    for (int d = 0; d < 16; d++) {
        ks_r[d] = Ksum_s[hb + d];
        kvc[d]  = KV_s[(hb + d) * 16 + dv];
    }

    float acc = 0.0f;
    const float* Qbase = g_Q + (size_t)n * (NQ * HID);

    #pragma unroll
    for (int c = 0; c < 5; c++) {
        #pragma unroll
        for (int i = 0; i < 16; i++)
            Qs[i][t] = Qbase[(c * 16 + i) * HID + t];
        __syncthreads();
        #pragma unroll
        for (int i = 0; i < 16; i++) {
            float zs = EPS, tmp = 0.0f;
            #pragma unroll
            for (int d = 0; d < 16; d++) {
                const float qd = Qs[i][hb + d];
                zs  += qd * ks_r[d];
                tmp += qd * kvc[d];
            }
            acc += __fdividef(tmp, zs);
        }
        __syncthreads();
    }

    out[(size_t)n * HID + t] = acc * (1.0f / NQ);
}

// ---------------------------------------------------------------------------
extern "C" void kernel_launch(void* const* d_in, const int* in_sizes, int n_in,
                              void* d_out, int out_size)
{
    const float* query = (const float*)d_in[0];
    const float* x     = (const float*)d_in[1];
    const float* guid  = (const float*)d_in[2];
    const float* Wq    = (const float*)d_in[3];
    const float* bq    = (const float*)d_in[4];
    const float* Wk    = (const float*)d_in[5];
    const float* bk    = (const float*)d_in[6];
    const float* Wv    = (const float*)d_in[7];
    const float* bv    = (const float*)d_in[8];
    float* out = (float*)d_out;

    // Weight prep: split + pad. Destinations are device globals selected in
    // DEVICE code via the MODE template (no device-symbol addresses on host).
    prep_w<0><<<128, 256>>>(Wk);
    prep_w<1><<<64, 256>>>(Wv);
    prep_w<2><<<128, 256>>>(Wq);

    // Projections (HMMA bf16 3-term split)
    gemm_mma<256, 0><<<1386, 256>>>(x, guid, bk);
    gemm_mma<128, 1><<<1386, 256>>>(x, nullptr, bv);
    gemm_mma<256, 2><<<1440, 256>>>(query, nullptr, bq);

    // Attention reduction -> out
    attn_kernel<<<NI, 128>>>(out);
}

// round 13
// speedup vs baseline: 3.5643x; 1.0359x over previous
#include <cuda_runtime.h>
#include <cuda_bf16.h>
#include <math.h>
#include <stdint.h>

#define NI 2304          // B*H*W
#define S_LEN 77
#define NQ 80
#define HID 128
#define EPS 1e-6f

typedef unsigned long long u64;

// ---------------- scratch (device globals; allocation-free) ----------------
__device__ float g_K[NI * S_LEN * HID];
__device__ float g_V[NI * S_LEN * HID];
__device__ float g_Q[NI * NQ * HID];

// Pre-split padded weight images: per 32-K chunk, 32 rows x 136 (128 + 8 pad) bf16.
#define B_STR 136
#define CHUNK_ELEMS (32 * B_STR)          // 4352 elems = 8704 bytes
__device__ __align__(16) __nv_bfloat16 g_Bk_hi[8 * CHUNK_ELEMS], g_Bk_lo[8 * CHUNK_ELEMS];
__device__ __align__(16) __nv_bfloat16 g_Bv_hi[4 * CHUNK_ELEMS], g_Bv_lo[4 * CHUNK_ELEMS];
__device__ __align__(16) __nv_bfloat16 g_Bq_hi[8 * CHUNK_ELEMS], g_Bq_lo[8 * CHUNK_ELEMS];

__device__ __forceinline__ float fmap(float t) {
    return t > 0.0f ? t + 1.0f : __expf(t);   // elu+1
}

__device__ __forceinline__ uint32_t s2u(const void* p) {
    uint32_t a;
    asm("{ .reg .u64 t; cvta.to.shared.u64 t, %1; cvt.u32.u64 %0, t; }" : "=r"(a) : "l"(p));
    return a;
}

#define LDSM_X4(r0, r1, r2, r3, addr) \
    asm volatile("ldmatrix.sync.aligned.m8n8.x4.shared.b16 {%0,%1,%2,%3}, [%4];" \
        : "=r"(r0), "=r"(r1), "=r"(r2), "=r"(r3) : "r"(addr))

#define LDSM_X4T(r0, r1, r2, r3, addr) \
    asm volatile("ldmatrix.sync.aligned.m8n8.x4.trans.shared.b16 {%0,%1,%2,%3}, [%4];" \
        : "=r"(r0), "=r"(r1), "=r"(r2), "=r"(r3) : "r"(addr))

#define MMA_BF16(d, a, b0, b1) \
    asm volatile("mma.sync.aligned.m16n8k16.row.col.f32.bf16.bf16.f32 " \
        "{%0,%1,%2,%3}, {%4,%5,%6,%7}, {%8,%9}, {%0,%1,%2,%3};" \
        : "+f"((d)[0]), "+f"((d)[1]), "+f"((d)[2]), "+f"((d)[3]) \
        : "r"((a)[0]), "r"((a)[1]), "r"((a)[2]), "r"((a)[3]), "r"(b0), "r"(b1))

#define CP_ASYNC16(dst, src) \
    asm volatile("cp.async.cg.shared.global [%0], [%1], 16;" :: "r"(dst), "l"(src) : "memory")
#define CP_COMMIT() asm volatile("cp.async.commit_group;" ::: "memory")
#define CP_WAIT0()  asm volatile("cp.async.wait_group 0;"  ::: "memory")
#define CP_WAIT1()  asm volatile("cp.async.wait_group 1;"  ::: "memory")

// ---------------------------------------------------------------------------
// Weight prep: truncation-split W(KDEPTH x 128) -> padded bf16 hi/lo chunk images.
// ---------------------------------------------------------------------------
template<int MODE>
__global__ void prep_w(const float* __restrict__ W)
{
    constexpr int NCHUNK = (MODE == 1) ? 4 : 8;
    __nv_bfloat16* hi = (MODE == 0) ? g_Bk_hi : (MODE == 1 ? g_Bv_hi : g_Bq_hi);
    __nv_bfloat16* lo = (MODE == 0) ? g_Bk_lo : (MODE == 1 ? g_Bv_lo : g_Bq_lo);

    int idx = blockIdx.x * 256 + threadIdx.x;
    if (idx >= NCHUNK * 4096) return;
    int c = idx >> 12;
    int r = (idx >> 7) & 31;
    int n = idx & 127;
    float v = W[(c * 32 + r) * 128 + n];
    uint32_t vb = __float_as_uint(v);
    float hf = __uint_as_float(vb & 0xFFFF0000u);
    hi[(c * 32 + r) * B_STR + n] = __ushort_as_bfloat16((unsigned short)(vb >> 16));
    lo[(c * 32 + r) * B_STR + n] = __float2bfloat16(v - hf);
}

// ---------------------------------------------------------------------------
// Pipelined HMMA bf16 split GEMM.  CTA 128x128, 8 warps (4M x 2N), K-chunk 32.
// A: register-prefetch one chunk ahead (LDG issued before compute).
// B: cp.async double-buffered, two chunks in flight.
// Dynamic smem layout (55808 B):
//   [0,512)        bias
//   [512,10752)    Ah (128 x 40 bf16)
//   [10752,20992)  Al
//   [20992,29696)  Bh buf0   [29696,38400) Bl buf0
//   [38400,47104)  Bh buf1   [47104,55808) Bl buf1
// ---------------------------------------------------------------------------
#define A_STR 40
#define OFF_AH   512
#define OFF_AL   10752
#define OFF_B(buf)  (20992 + (buf) * 17408)          // Bh of buffer
#define OFF_BL(buf) (29696 + (buf) * 17408)          // Bl of buffer
#define SMEM_SZ  55808

template<int KDEPTH, int MODE>
__global__ __launch_bounds__(256, 2)
void gemm_mma(const float* __restrict__ A1, const float* __restrict__ A2,
              const float* __restrict__ bias)
{
    extern __shared__ __align__(16) char smem[];
    constexpr int NC = KDEPTH / 32;

    float* outp = (MODE == 0) ? g_K : (MODE == 1 ? g_V : g_Q);
    const __nv_bfloat16* img_hi = (MODE == 0) ? g_Bk_hi : (MODE == 1 ? g_Bv_hi : g_Bq_hi);
    const __nv_bfloat16* img_lo = (MODE == 0) ? g_Bk_lo : (MODE == 1 ? g_Bv_lo : g_Bq_lo);

    const int t    = threadIdx.x;
    const int lane = t & 31;
    const int wid  = t >> 5;
    const int wm   = wid & 3;
    const int wn   = wid >> 2;
    const int m0   = blockIdx.x * 128;

    if (t < 128) ((float*)smem)[t] = bias[t];

    const uint32_t sb = s2u(smem);

    // Hoisted A row pointers (4 rows per thread: r = (t>>3) + it*32)
    const int k4     = (t & 7) << 2;
    const int r_base = t >> 3;
    const float* rowp[4];
    ptrdiff_t gdelta = 0;
    #pragma unroll
    for (int it = 0; it < 4; it++) {
        int r = r_base + it * 32;
        int m = m0 + r;
        if (MODE == 2) {
            int ni = m / NQ; int l = m - ni * NQ;
            int b = ni / 576; int rem = ni - b * 576;
            rowp[it] = A1 + (size_t)((b * NQ + l) * 576 + rem) * 256;
        } else {
            rowp[it] = A1 + (size_t)m * 128;
        }
    }
    if (MODE == 0) gdelta = A2 - A1;

    float acc[2][8][4];
    #pragma unroll
    for (int mt = 0; mt < 2; mt++)
        #pragma unroll
        for (int nt = 0; nt < 8; nt++)
            #pragma unroll
            for (int j = 0; j < 4; j++) acc[mt][nt][j] = 0.0f;

    const int l15 = lane & 15;
    const int l16 = (lane >> 4) * 8;

    float4 apf[4];   // A prefetch registers

    // ---- helpers (lambdas inline) ----
    auto lda = [&](int c) {
        const int kg = c * 32 + k4;
        #pragma unroll
        for (int it = 0; it < 4; it++) {
            const float* src;
            if (MODE == 0)
                src = (kg >= 128) ? (rowp[it] + gdelta + (kg - 128)) : (rowp[it] + kg);
            else
                src = rowp[it] + kg;
            apf[it] = *(const float4*)src;
        }
    };
    auto sta = [&]() {
        #pragma unroll
        for (int it = 0; it < 4; it++) {
            float4 v = apf[it];
            uint32_t bx = __float_as_uint(v.x), by = __float_as_uint(v.y);
            uint32_t bz = __float_as_uint(v.z), bw = __float_as_uint(v.w);
            uint32_t hi01, hi23, lo01, lo23;
            asm("prmt.b32 %0, %1, %2, 0x7632;" : "=r"(hi01) : "r"(bx), "r"(by));
            asm("prmt.b32 %0, %1, %2, 0x7632;" : "=r"(hi23) : "r"(bz), "r"(bw));
            float lx = v.x - __uint_as_float(bx & 0xFFFF0000u);
            float ly = v.y - __uint_as_float(by & 0xFFFF0000u);
            float lz = v.z - __uint_as_float(bz & 0xFFFF0000u);
            float lw = v.w - __uint_as_float(bw & 0xFFFF0000u);
            asm("cvt.rn.bf16x2.f32 %0, %1, %2;" : "=r"(lo01) : "f"(ly), "f"(lx));
            asm("cvt.rn.bf16x2.f32 %0, %1, %2;" : "=r"(lo23) : "f"(lw), "f"(lz));
            int off = (r_base + it * 32) * (A_STR * 2) + k4 * 2;
            *(u64*)(smem + OFF_AH + off) = (u64)hi01 | ((u64)hi23 << 32);
            *(u64*)(smem + OFF_AL + off) = (u64)lo01 | ((u64)lo23 << 32);
        }
    };
    auto ldb = [&](int c, int buf) {
        const char* ih = (const char*)img_hi + (size_t)c * 8704;
        const char* il = (const char*)img_lo + (size_t)c * 8704;
        const uint32_t bh = sb + OFF_B(buf), bl = sb + OFF_BL(buf);
        for (int i = t; i < 1088; i += 256) {
            bool isHi = i < 544;
            int o = (isHi ? i : i - 544) * 16;
            CP_ASYNC16((isHi ? bh : bl) + o, (isHi ? ih : il) + o);
        }
        CP_COMMIT();
    };
    auto compute = [&](int buf) {
        const uint32_t sBh = sb + OFF_B(buf), sBl = sb + OFF_BL(buf);
        const uint32_t sAh = sb + OFF_AH,    sAl = sb + OFF_AL;
        #pragma unroll
        for (int ks = 0; ks < 2; ks++) {
            uint32_t bh[4][4], bl[4][4];
            #pragma unroll
            for (int ng = 0; ng < 4; ng++) {
                uint32_t ba = (uint32_t)((ks * 16 + l15) * (B_STR * 2)
                             + (wn * 64 + ng * 16 + l16) * 2);
                LDSM_X4T(bh[ng][0], bh[ng][1], bh[ng][2], bh[ng][3], sBh + ba);
                LDSM_X4T(bl[ng][0], bl[ng][1], bl[ng][2], bl[ng][3], sBl + ba);
            }
            #pragma unroll
            for (int mt = 0; mt < 2; mt++) {
                uint32_t aa = (uint32_t)((wm * 32 + mt * 16 + l15) * (A_STR * 2)
                             + (ks * 16 + l16) * 2);
                uint32_t ah[4], al[4];
                LDSM_X4(ah[0], ah[1], ah[2], ah[3], sAh + aa);
                LDSM_X4(al[0], al[1], al[2], al[3], sAl + aa);
                #pragma unroll
                for (int nt = 0; nt < 8; nt++) {
                    const int ng = nt >> 1, hf = (nt & 1) * 2;
                    MMA_BF16(acc[mt][nt], ah, bh[ng][hf], bh[ng][hf + 1]);
                    MMA_BF16(acc[mt][nt], ah, bl[ng][hf], bl[ng][hf + 1]);
                    MMA_BF16(acc[mt][nt], al, bh[ng][hf], bh[ng][hf + 1]);
                }
            }
        }
    };

    // ---- prologue: A0 + B0, B1 in flight ----
    lda(0);
    ldb(0, 0);
    if (NC > 1) ldb(1, 1);
    sta();
    if (NC > 1) CP_WAIT1(); else CP_WAIT0();
    __syncthreads();

    // ---- pipelined main loop ----
    #pragma unroll
    for (int c = 0; c < NC; c++) {
        if (c + 1 < NC) lda(c + 1);          // issue next A loads before compute
        compute(c & 1);
        __syncthreads();                      // A smem + B buf (c&1) free
        if (c + 1 < NC) {
            sta();                            // next A into smem
            if (c + 2 < NC) {
                ldb(c + 2, c & 1);            // refill freed B buffer
                CP_WAIT1();                   // B(c+1) guaranteed complete
            } else {
                CP_WAIT0();
            }
            __syncthreads();
        }
    }

    // ---- epilogue: bias (+fmap), direct global stores ----
    const float* bias_s = (const float*)smem;
    const int r4 = lane >> 2;
    const int c2 = (lane & 3) * 2;
    #pragma unroll
    for (int mt = 0; mt < 2; mt++) {
        #pragma unroll
        for (int nt = 0; nt < 8; nt++) {
            const int col = wn * 64 + nt * 8 + c2;
            const float b0 = bias_s[col], b1 = bias_s[col + 1];
            const int row0 = m0 + wm * 32 + mt * 16 + r4;
            float2 o0, o1;
            o0.x = acc[mt][nt][0] + b0;  o0.y = acc[mt][nt][1] + b1;
            o1.x = acc[mt][nt][2] + b0;  o1.y = acc[mt][nt][3] + b1;
            if (MODE != 1) {
                o0.x = fmap(o0.x); o0.y = fmap(o0.y);
                o1.x = fmap(o1.x); o1.y = fmap(o1.y);
            }
            *(float2*)(outp + (size_t)row0 * 128 + col)       = o0;
            *(float2*)(outp + (size_t)(row0 + 8) * 128 + col) = o1;
        }
    }
}

// ---------------------------------------------------------------------------
// Attention reduction (round-12 version: FFMA2 pass 1, register-hoisted pass 2)
// ---------------------------------------------------------------------------
__device__ __forceinline__ u64 pack2(float lo, float hi) {
    u64 r; asm("mov.b64 %0, {%1, %2};" : "=l"(r) : "f"(lo), "f"(hi)); return r;
}
__device__ __forceinline__ u64 fma2(u64 a, u64 b, u64 c) {
    u64 d; asm("fma.rn.f32x2 %0, %1, %2, %3;" : "=l"(d) : "l"(a), "l"(b), "l"(c)); return d;
}
__device__ __forceinline__ float2 unpack2(u64 v) {
    float2 f; asm("mov.b64 {%0, %1}, %2;" : "=f"(f.x), "=f"(f.y) : "l"(v)); return f;
}

__global__ __launch_bounds__(128)
void attn_kernel(float* __restrict__ out)
{
    __shared__ float KV_s[HID * 16];
    __shared__ float Ksum_s[HID];
    __shared__ float Qs[16][HID];

    const int n  = blockIdx.x;
    const int t  = threadIdx.x;
    const int h  = t >> 4;
    const int dv = t & 15;

    const float* Kp = g_K + (size_t)n * (S_LEN * HID);
    const float* Vp = g_V + (size_t)n * (S_LEN * HID) + h * 16;

    u64 kv2[8];
    #pragma unroll
    for (int j = 0; j < 8; j++) kv2[j] = 0ULL;
    float ksum = 0.0f;

    #pragma unroll 4
    for (int s = 0; s < S_LEN; s++) {
        const float kd = Kp[s * HID + t];
        const float* vrow = Vp + s * HID;
        const ulonglong2 p0 = *(const ulonglong2*)(vrow);
        const ulonglong2 p1 = *(const ulonglong2*)(vrow + 4);
        const ulonglong2 p2 = *(const ulonglong2*)(vrow + 8);
        const ulonglong2 p3 = *(const ulonglong2*)(vrow + 12);
        ksum += kd;
        const u64 kd2 = pack2(kd, kd);
        kv2[0] = fma2(kd2, p0.x, kv2[0]);
        kv2[1] = fma2(kd2, p0.y, kv2[1]);
        kv2[2] = fma2(kd2, p1.x, kv2[2]);
        kv2[3] = fma2(kd2, p1.y, kv2[3]);
        kv2[4] = fma2(kd2, p2.x, kv2[4]);
        kv2[5] = fma2(kd2, p2.y, kv2[5]);
        kv2[6] = fma2(kd2, p3.x, kv2[6]);
        kv2[7] = fma2(kd2, p3.y, kv2[7]);
    }
    Ksum_s[t] = ksum;
    #pragma unroll
    for (int j = 0; j < 8; j++) {
        float2 p = unpack2(kv2[j]);
        KV_s[t * 16 + 2 * j]     = p.x;
        KV_s[t * 16 + 2 * j + 1] = p.y;
    }
    __syncthreads();

    const int hb = h * 16;
    float ks_r[16], kvc[16];
    #pragma unroll
    for (int d = 0; d < 16; d++) {
        ks_r[d] = Ksum_s[hb + d];
        kvc[d]  = KV_s[(hb + d) * 16 + dv];
    }

    float acc = 0.0f;
    const float* Qbase = g_Q + (size_t)n * (NQ * HID);

    #pragma unroll
    for (int c = 0; c < 5; c++) {
        #pragma unroll
        for (int i = 0; i < 16; i++)
            Qs[i][t] = Qbase[(c * 16 + i) * HID + t];
        __syncthreads();
        #pragma unroll
        for (int i = 0; i < 16; i++) {
            float zs = EPS, tmp = 0.0f;
            #pragma unroll
            for (int d = 0; d < 16; d++) {
                const float qd = Qs[i][hb + d];
                zs  += qd * ks_r[d];
                tmp += qd * kvc[d];
            }
            acc += __fdividef(tmp, zs);
        }
        __syncthreads();
    }

    out[(size_t)n * HID + t] = acc * (1.0f / NQ);
}

// ---------------------------------------------------------------------------
extern "C" void kernel_launch(void* const* d_in, const int* in_sizes, int n_in,
                              void* d_out, int out_size)
{
    const float* query = (const float*)d_in[0];
    const float* x     = (const float*)d_in[1];
    const float* guid  = (const float*)d_in[2];
    const float* Wq    = (const float*)d_in[3];
    const float* bq    = (const float*)d_in[4];
    const float* Wk    = (const float*)d_in[5];
    const float* bk    = (const float*)d_in[6];
    const float* Wv    = (const float*)d_in[7];
    const float* bv    = (const float*)d_in[8];
    float* out = (float*)d_out;

    static bool attr_done = false;
    if (!attr_done) {
        cudaFuncSetAttribute(gemm_mma<256,0>, cudaFuncAttributeMaxDynamicSharedMemorySize, SMEM_SZ);
        cudaFuncSetAttribute(gemm_mma<128,1>, cudaFuncAttributeMaxDynamicSharedMemorySize, SMEM_SZ);
        cudaFuncSetAttribute(gemm_mma<256,2>, cudaFuncAttributeMaxDynamicSharedMemorySize, SMEM_SZ);
        attr_done = true;
    }

    // Weight prep (destinations selected in device code)
    prep_w<0><<<128, 256>>>(Wk);
    prep_w<1><<<64, 256>>>(Wv);
    prep_w<2><<<128, 256>>>(Wq);

    // Pipelined projections
    gemm_mma<256, 0><<<1386, 256, SMEM_SZ>>>(x, guid, bk);
    gemm_mma<128, 1><<<1386, 256, SMEM_SZ>>>(x, nullptr, bv);
    gemm_mma<256, 2><<<1440, 256, SMEM_SZ>>>(query, nullptr, bq);

    // Attention reduction -> out
    attn_kernel<<<NI, 128>>>(out);
}